// round 16
// baseline (speedup 1.0000x reference)
#include <cuda_runtime.h>
#include <cuda_fp16.h>
#include <cstdint>
#include <math.h>

#define N_TOK 2048
#define DIM   1024
#define NEXP  8
#define IDIM  2048
#define CAP   2048
// 1KB align slack + 3 stages x (A, B) x 16KB
#define SMEM_SZ (1024 + 3*2*16384)

// ---------------- baseline-PTX helpers (no 'a'-arch instructions) ----------
__device__ __forceinline__ uint32_t smem_u32(const void* p) {
    uint32_t a;
    asm("{ .reg .u64 t; cvta.to.shared.u64 t, %1; cvt.u32.u64 %0, t; }" : "=r"(a) : "l"(p));
    return a;
}
#define CPA16(dst, src) \
    asm volatile("cp.async.cg.shared.global [%0], [%1], 16;" :: "r"(dst), "l"(src))
#define CPA_COMMIT() asm volatile("cp.async.commit_group;" ::: "memory")
#define CPA_WAIT0()  asm volatile("cp.async.wait_group 0;" ::: "memory")
#define CPA_WAIT1()  asm volatile("cp.async.wait_group 1;" ::: "memory")

__device__ __forceinline__ void ldsm4(uint32_t* r, uint32_t addr) {
    asm volatile("ldmatrix.sync.aligned.m8n8.x4.shared.b16 {%0,%1,%2,%3}, [%4];"
        : "=r"(r[0]), "=r"(r[1]), "=r"(r[2]), "=r"(r[3]) : "r"(addr));
}
__device__ __forceinline__ void mma16816(float* c, const uint32_t* a, const uint32_t* b) {
    asm volatile("mma.sync.aligned.m16n8k16.row.col.f32.f16.f16.f32 "
        "{%0,%1,%2,%3}, {%4,%5,%6,%7}, {%8,%9}, {%0,%1,%2,%3};"
        : "+f"(c[0]), "+f"(c[1]), "+f"(c[2]), "+f"(c[3])
        : "r"(a[0]), "r"(a[1]), "r"(a[2]), "r"(a[3]), "r"(b[0]), "r"(b[1]));
}
#define SWZ(o) ((o) ^ (((o) >> 3) & 0x70))

// ---------------- scratch globals ----------------
__device__ int   g_cnt[NEXP];
__device__ int   g_tok[NEXP * CAP];
__device__ float g_w[NEXP * CAP];
__device__ __half g_x16[N_TOK * DIM];
__device__ __half g_wgu16[(size_t)NEXP * 2 * IDIM * DIM];
__device__ __half g_wd16[(size_t)NEXP * DIM * IDIM];
__device__ __half g_act16[(size_t)NEXP * CAP * IDIM];

// ---------------- small kernels ----------------
__global__ void k_init_y(float* __restrict__ y) {
    int idx = blockIdx.x * blockDim.x + threadIdx.x;
    if (idx < N_TOK * DIM) y[idx] = 0.f;
}

__global__ void k_cvt_h(const float4* __restrict__ s, uint2* __restrict__ o, int n4) {
    for (int i = blockIdx.x * blockDim.x + threadIdx.x; i < n4; i += gridDim.x * blockDim.x) {
        float4 v = s[i];
        __half2 p0 = __floats2half2_rn(v.x, v.y);
        __half2 p1 = __floats2half2_rn(v.z, v.w);
        o[i] = make_uint2(*(uint32_t*)&p0, *(uint32_t*)&p1);
    }
}

// fused prologue: one warp per token. Reads x once; writes x16 row AND
// computes router logits -> top4 -> softmax -> scatter.
// REQUIRES g_cnt pre-zeroed (memset node on the same stream).
__global__ void k_prolog(const float* __restrict__ x, const float* __restrict__ rw,
                         const float* __restrict__ rb, uint2* __restrict__ x16o) {
    int gw = (blockIdx.x * blockDim.x + threadIdx.x) >> 5;
    int lane = threadIdx.x & 31;
    if (gw >= N_TOK) return;
    const float4* xr = (const float4*)(x + (size_t)gw * DIM);
    uint2* xo = x16o + (size_t)gw * (DIM / 4);
    float acc[NEXP];
#pragma unroll
    for (int e = 0; e < NEXP; e++) acc[e] = 0.f;
#pragma unroll
    for (int it = 0; it < DIM / (32 * 4); it++) {
        int q = it * 32 + lane;                 // float4 index within row
        float4 xv = xr[q];
        __half2 p0 = __floats2half2_rn(xv.x, xv.y);
        __half2 p1 = __floats2half2_rn(xv.z, xv.w);
        xo[q] = make_uint2(*(uint32_t*)&p0, *(uint32_t*)&p1);
#pragma unroll
        for (int e = 0; e < NEXP; e++) {
            float4 wv = ((const float4*)(rw + e * DIM))[q];
            acc[e] = fmaf(xv.x, wv.x, acc[e]);
            acc[e] = fmaf(xv.y, wv.y, acc[e]);
            acc[e] = fmaf(xv.z, wv.z, acc[e]);
            acc[e] = fmaf(xv.w, wv.w, acc[e]);
        }
    }
#pragma unroll
    for (int e = 0; e < NEXP; e++)
#pragma unroll
        for (int off = 16; off; off >>= 1) acc[e] += __shfl_down_sync(0xffffffffu, acc[e], off);
    if (lane == 0) {
        float lg[NEXP];
#pragma unroll
        for (int e = 0; e < NEXP; e++) lg[e] = acc[e] + rb[e];
        int sel[4]; float sv[4]; unsigned used = 0;
#pragma unroll
        for (int k = 0; k < 4; k++) {
            int bi = 0; float bv = -3.4e38f;
#pragma unroll
            for (int e = 0; e < NEXP; e++)
                if (!((used >> e) & 1u) && lg[e] > bv) { bv = lg[e]; bi = e; }
            used |= (1u << bi); sel[k] = bi; sv[k] = bv;
        }
        float s = 0.f, ex[4];
#pragma unroll
        for (int k = 0; k < 4; k++) { ex[k] = __expf(sv[k] - sv[0]); s += ex[k]; }
        float inv = 1.f / s;
#pragma unroll
        for (int k = 0; k < 4; k++) {
            int e = sel[k];
            int pos = atomicAdd(&g_cnt[e], 1);
            g_tok[e * CAP + pos] = gw;
            g_w[e * CAP + pos] = ex[k] * inv;
        }
    }
}

// ---------------- gate_up grouped GEMM (single fp16, 3-stage) --------------
// Experts [e0, e0+gridDim.z). CTA: 128 tokens x (64g + 64u). 16 k-chunks.
__global__ __launch_bounds__(256, 2) void k_gateup(const float* __restrict__ bgu, int e0) {
    int e = e0 + blockIdx.z;
    int cnt = g_cnt[e];
    int m0 = blockIdx.y * 128;
    if (m0 >= cnt) return;
    int n0 = blockIdx.x * 64;

    extern __shared__ char dsm[];
    __shared__ int s_tok[128];
    int t = threadIdx.x;
    uint32_t dyn = smem_u32(dsm);
    uint32_t tb = (dyn + 1023) & ~1023u;

    if (t < 128) {
        int r = m0 + t; if (r >= cnt) r = cnt - 1;
        s_tok[t] = g_tok[e * CAP + r];
    }
    __syncthreads();

    const __half* wgu = g_wgu16 + (size_t)e * 2 * IDIM * DIM;

    auto issue = [&](int c) {
        int col0 = c * 64;
        uint32_t base = tb + (c % 3) * 32768;
#pragma unroll
        for (int it = 0; it < 4; it++) {
            int idx = it * 256 + t; int r = idx >> 3; int gq = idx & 7;
            uint32_t off = SWZ(r * 128 + gq * 16);
            CPA16(base + off, g_x16 + (size_t)s_tok[r] * DIM + col0 + gq * 8);
        }
#pragma unroll
        for (int it = 0; it < 4; it++) {
            int idx = it * 256 + t; int r = idx >> 3; int gq = idx & 7;
            uint32_t off = SWZ(r * 128 + gq * 16);
            int wrow = (r < 64) ? (n0 + r) : (IDIM + n0 + r - 64);
            CPA16(base + 16384 + off, wgu + (size_t)wrow * DIM + col0 + gq * 8);
        }
        CPA_COMMIT();
    };

    int warp = t >> 5, lane = t & 31;
    int wm = warp & 3, wn = warp >> 2;
    float accg[2][4][4] = {}, accu[2][4][4] = {};

    // pre-swizzled lane bases; k-step applied with XOR (bits 5-6 of unswizzled
    // base are 0, swizzle mask depends only on row bits -> SWZ(x+ko)==SWZ(x)^ko)
    uint32_t arow[2], grow[2], urow[2];
#pragma unroll
    for (int mt = 0; mt < 2; mt++)
        arow[mt] = SWZ((wm * 32 + mt * 16 + (lane & 15)) * 128 + ((lane >> 4) << 4));
#pragma unroll
    for (int nt = 0; nt < 2; nt++) {
        int rg = wn * 32 + nt * 16 + ((lane >> 4) << 3) + (lane & 7);
        uint32_t kb = ((lane >> 3) & 1) << 4;
        grow[nt] = SWZ(rg * 128 + kb);
        urow[nt] = SWZ((rg + 64) * 128 + kb);
    }

    const int NC = 16;
    issue(0); issue(1);
    for (int c = 0; c < NC; c++) {
        if (c + 1 < NC) CPA_WAIT1(); else CPA_WAIT0();
        __syncthreads();
        if (c + 2 < NC) issue(c + 2);
        uint32_t base = tb + (c % 3) * 32768;
#pragma unroll
        for (int kk = 0; kk < 4; kk++) {
            uint32_t ko = kk * 32;
            uint32_t ah[2][4], bg[2][4], bu[2][4];
#pragma unroll
            for (int mt = 0; mt < 2; mt++) ldsm4(ah[mt], base + (arow[mt] ^ ko));
#pragma unroll
            for (int nt = 0; nt < 2; nt++) {
                ldsm4(bg[nt], base + 16384 + (grow[nt] ^ ko));
                ldsm4(bu[nt], base + 16384 + (urow[nt] ^ ko));
            }
#pragma unroll
            for (int mt = 0; mt < 2; mt++)
#pragma unroll
                for (int nt = 0; nt < 4; nt++) {
                    mma16816(accg[mt][nt], ah[mt], &bg[nt >> 1][(nt & 1) * 2]);
                    mma16816(accu[mt][nt], ah[mt], &bu[nt >> 1][(nt & 1) * 2]);
                }
        }
    }

    // epilogue: bias + clamped SwiGLU -> fp16 activations
#pragma unroll
    for (int mt = 0; mt < 2; mt++) {
        int r0 = m0 + wm * 32 + mt * 16 + (lane >> 2);
        int r1 = r0 + 8;
#pragma unroll
        for (int nt = 0; nt < 4; nt++) {
            int jg = n0 + wn * 32 + nt * 8 + (lane & 3) * 2;
            float bg0 = bgu[e * 2 * IDIM + jg],        bg1 = bgu[e * 2 * IDIM + jg + 1];
            float bu0 = bgu[e * 2 * IDIM + IDIM + jg], bu1 = bgu[e * 2 * IDIM + IDIM + jg + 1];
#pragma unroll
            for (int hh = 0; hh < 2; hh++) {
                int r = hh ? r1 : r0;
                if (r >= cnt) continue;
                float g0 = accg[mt][nt][hh * 2 + 0] + bg0;
                float g1 = accg[mt][nt][hh * 2 + 1] + bg1;
                float u0 = accu[mt][nt][hh * 2 + 0] + bu0;
                float u1 = accu[mt][nt][hh * 2 + 1] + bu1;
                g0 = fminf(g0, 7.f); g1 = fminf(g1, 7.f);
                u0 = fminf(fmaxf(u0, -7.f), 7.f); u1 = fminf(fmaxf(u1, -7.f), 7.f);
                float a0 = (u0 + 1.f) * g0 / (1.f + __expf(-1.702f * g0));
                float a1 = (u1 + 1.f) * g1 / (1.f + __expf(-1.702f * g1));
                __half2 hv = __floats2half2_rn(a0, a1);
                *(uint32_t*)(g_act16 + ((size_t)e * CAP + r) * IDIM + jg) = *(uint32_t*)&hv;
            }
        }
    }
}

// ---------------- down grouped GEMM (single fp16, 3-stage) + combine ------
// Experts [e0, e0+gridDim.z). CTA: 128 tokens x 128 out dims. 32 k-chunks.
__global__ __launch_bounds__(256, 2) void k_down(const float* __restrict__ bd,
                                                 float* __restrict__ y, int e0) {
    int e = e0 + blockIdx.z;
    int cnt = g_cnt[e];
    int m0 = blockIdx.y * 128;
    if (m0 >= cnt) return;
    int nn0 = blockIdx.x * 128;

    extern __shared__ char dsm[];
    int t = threadIdx.x;
    uint32_t dyn = smem_u32(dsm);
    uint32_t tb = (dyn + 1023) & ~1023u;

    const __half* a_g = g_act16 + ((size_t)e * CAP + m0) * IDIM;
    const __half* wd  = g_wd16 + (size_t)e * DIM * IDIM;

    auto issue = [&](int c) {
        int col0 = c * 64;
        uint32_t base = tb + (c % 3) * 32768;
#pragma unroll
        for (int it = 0; it < 4; it++) {
            int idx = it * 256 + t; int r = idx >> 3; int gq = idx & 7;
            uint32_t off = SWZ(r * 128 + gq * 16);
            CPA16(base + off, a_g + (size_t)r * IDIM + col0 + gq * 8);
        }
#pragma unroll
        for (int it = 0; it < 4; it++) {
            int idx = it * 256 + t; int r = idx >> 3; int gq = idx & 7;
            uint32_t off = SWZ(r * 128 + gq * 16);
            CPA16(base + 16384 + off, wd + (size_t)(nn0 + r) * IDIM + col0 + gq * 8);
        }
        CPA_COMMIT();
    };

    int warp = t >> 5, lane = t & 31;
    int wm = warp & 3, wn = warp >> 2;
    float acc[2][8][4] = {};

    uint32_t arow[2], brow[4];
#pragma unroll
    for (int mt = 0; mt < 2; mt++)
        arow[mt] = SWZ((wm * 32 + mt * 16 + (lane & 15)) * 128 + ((lane >> 4) << 4));
#pragma unroll
    for (int nt = 0; nt < 4; nt++) {
        int rb_ = wn * 64 + nt * 16 + ((lane >> 4) << 3) + (lane & 7);
        brow[nt] = SWZ(rb_ * 128 + (((lane >> 3) & 1) << 4));
    }

    const int NC = 32;
    issue(0); issue(1);
    for (int c = 0; c < NC; c++) {
        if (c + 1 < NC) CPA_WAIT1(); else CPA_WAIT0();
        __syncthreads();
        if (c + 2 < NC) issue(c + 2);
        uint32_t base = tb + (c % 3) * 32768;
#pragma unroll
        for (int kk = 0; kk < 4; kk++) {
            uint32_t ko = kk * 32;
            uint32_t ah[2][4], b[4][4];
#pragma unroll
            for (int mt = 0; mt < 2; mt++) ldsm4(ah[mt], base + (arow[mt] ^ ko));
#pragma unroll
            for (int nt = 0; nt < 4; nt++) ldsm4(b[nt], base + 16384 + (brow[nt] ^ ko));
#pragma unroll
            for (int mt = 0; mt < 2; mt++)
#pragma unroll
                for (int nt = 0; nt < 8; nt++)
                    mma16816(acc[mt][nt], ah[mt], &b[nt >> 1][(nt & 1) * 2]);
        }
    }

    // epilogue: + bias, * combine weight, atomicAdd into y
#pragma unroll
    for (int mt = 0; mt < 2; mt++) {
        int r0 = m0 + wm * 32 + mt * 16 + (lane >> 2);
        int r1 = r0 + 8;
        int   tok0 = 0, tok1 = 0; float w0 = 0.f, w1 = 0.f;
        bool v0 = r0 < cnt, v1 = r1 < cnt;
        if (v0) { tok0 = g_tok[e * CAP + r0]; w0 = g_w[e * CAP + r0]; }
        if (v1) { tok1 = g_tok[e * CAP + r1]; w1 = g_w[e * CAP + r1]; }
#pragma unroll
        for (int nt = 0; nt < 8; nt++) {
            int n = nn0 + wn * 64 + nt * 8 + (lane & 3) * 2;
            float b0 = bd[e * DIM + n], b1 = bd[e * DIM + n + 1];
            if (v0) {
                atomicAdd(&y[(size_t)tok0 * DIM + n],     w0 * (acc[mt][nt][0] + b0));
                atomicAdd(&y[(size_t)tok0 * DIM + n + 1], w0 * (acc[mt][nt][1] + b1));
            }
            if (v1) {
                atomicAdd(&y[(size_t)tok1 * DIM + n],     w1 * (acc[mt][nt][2] + b0));
                atomicAdd(&y[(size_t)tok1 * DIM + n + 1], w1 * (acc[mt][nt][3] + b1));
            }
        }
    }
}

// ---------------------------------------------------------------------------
extern "C" void kernel_launch(void* const* d_in, const int* in_sizes, int n_in,
                              void* d_out, int out_size) {
    const float* x   = (const float*)d_in[0];
    const float* rw  = (const float*)d_in[1];
    const float* rb  = (const float*)d_in[2];
    const float* wgu = (const float*)d_in[3];
    const float* bgu = (const float*)d_in[4];
    const float* wd  = (const float*)d_in[5];
    const float* bd  = (const float*)d_in[6];
    float* y = (float*)d_out;

    // one-time setup — same 2-side-stream resource set as the passing rounds
    static cudaStream_t s2 = nullptr, s3 = nullptr;
    static cudaEvent_t ev_root = nullptr, ev_main = nullptr, ev_wguA = nullptr,
                       ev_wd = nullptr, ev_d2 = nullptr, ev_d3 = nullptr;
    static int* cnt_ptr = nullptr;
    if (!s2) {
        cudaStreamCreateWithFlags(&s2, cudaStreamNonBlocking);
        cudaStreamCreateWithFlags(&s3, cudaStreamNonBlocking);
        cudaEventCreateWithFlags(&ev_root, cudaEventDisableTiming);
        cudaEventCreateWithFlags(&ev_main, cudaEventDisableTiming);
        cudaEventCreateWithFlags(&ev_wguA, cudaEventDisableTiming);
        cudaEventCreateWithFlags(&ev_wd, cudaEventDisableTiming);
        cudaEventCreateWithFlags(&ev_d2, cudaEventDisableTiming);
        cudaEventCreateWithFlags(&ev_d3, cudaEventDisableTiming);
        cudaGetSymbolAddress((void**)&cnt_ptr, g_cnt);
        cudaFuncSetAttribute(k_gateup, cudaFuncAttributeMaxDynamicSharedMemorySize, SMEM_SZ);
        cudaFuncSetAttribute(k_down,   cudaFuncAttributeMaxDynamicSharedMemorySize, SMEM_SZ);
    }

    __half *x16, *gu16, *wd16;
    cudaGetSymbolAddress((void**)&x16,  g_x16);
    cudaGetSymbolAddress((void**)&gu16, g_wgu16);
    cudaGetSymbolAddress((void**)&wd16, g_wd16);

    const size_t WGU_E = (size_t)2 * IDIM * DIM;   // wgu elems per expert

    // fork side streams off the main (capture) stream
    cudaEventRecord(ev_root, 0);
    cudaStreamWaitEvent(s2, ev_root, 0);
    cudaStreamWaitEvent(s3, ev_root, 0);

    // s3: chain-A wgu slice first (unblocks main ASAP), then chain-C slice,
    //     then y-zero + wd conversion (all done long before any down runs)
    k_cvt_h<<<3072, 256, 0, s3>>>((const float4*)(wgu),
                                  (uint2*)(gu16), (int)(3 * WGU_E / 4));
    cudaEventRecord(ev_wguA, s3);
    k_cvt_h<<<2048, 256, 0, s3>>>((const float4*)(wgu + 6 * WGU_E),
                                  (uint2*)(gu16 + 6 * WGU_E), (int)(2 * WGU_E / 4));
    k_init_y<<<(N_TOK * DIM + 255) / 256, 256, 0, s3>>>(y);
    k_cvt_h<<<4096, 256, 0, s3>>>((const float4*)wd, (uint2*)wd16, NEXP * DIM * IDIM / 4);
    cudaEventRecord(ev_wd, s3);

    // s2: chain-B wgu slice (in-stream for its own gateups)
    k_cvt_h<<<3072, 256, 0, s2>>>((const float4*)(wgu + 3 * WGU_E),
                                  (uint2*)(gu16 + 3 * WGU_E), (int)(3 * WGU_E / 4));

    // main: zero counters (memset node) -> fused router + x conversion
    cudaMemsetAsync(cnt_ptr, 0, NEXP * sizeof(int), 0);
    k_prolog<<<(N_TOK * 32) / 256, 256>>>(x, rw, rb, (uint2*)x16);
    cudaEventRecord(ev_main, 0);

    // ---- 3 expert chains, each: ALL gateups first, then ALL downs ----
    // chain A (main, experts 0-2)
    cudaStreamWaitEvent(0, ev_wguA, 0);
    k_gateup<<<dim3(IDIM / 64, CAP / 128, 3), 256, SMEM_SZ>>>(bgu, 0);
    cudaStreamWaitEvent(0, ev_wd, 0);
    k_down<<<dim3(DIM / 128, CAP / 128, 3), 256, SMEM_SZ>>>(bd, y, 0);

    // chain B (s2, experts 3-5)
    cudaStreamWaitEvent(s2, ev_main, 0);
    k_gateup<<<dim3(IDIM / 64, CAP / 128, 3), 256, SMEM_SZ, s2>>>(bgu, 3);
    cudaStreamWaitEvent(s2, ev_wd, 0);
    k_down<<<dim3(DIM / 128, CAP / 128, 3), 256, SMEM_SZ, s2>>>(bd, y, 3);
    cudaEventRecord(ev_d2, s2);

    // chain C (s3, experts 6-7): wgu slice, wd and y are all in-stream
    cudaStreamWaitEvent(s3, ev_main, 0);
    k_gateup<<<dim3(IDIM / 64, CAP / 128, 2), 256, SMEM_SZ, s3>>>(bgu, 6);
    k_down<<<dim3(DIM / 128, CAP / 128, 2), 256, SMEM_SZ, s3>>>(bd, y, 6);
    cudaEventRecord(ev_d3, s3);

    // join side chains back into the main stream
    cudaStreamWaitEvent(0, ev_d2, 0);
    cudaStreamWaitEvent(0, ev_d3, 0);
}

// round 17
// speedup vs baseline: 1.0049x; 1.0049x over previous
#include <cuda_runtime.h>
#include <cuda_fp16.h>
#include <cstdint>
#include <math.h>

#define N_TOK 2048
#define DIM   1024
#define NEXP  8
#define IDIM  2048
#define CAP   2048
// 1KB align slack + 3 stages x (A, B) x 16KB
#define SMEM_SZ (1024 + 3*2*16384)

// ---------------- baseline-PTX helpers (no 'a'-arch instructions) ----------
__device__ __forceinline__ uint32_t smem_u32(const void* p) {
    uint32_t a;
    asm("{ .reg .u64 t; cvta.to.shared.u64 t, %1; cvt.u32.u64 %0, t; }" : "=r"(a) : "l"(p));
    return a;
}
#define CPA16(dst, src) \
    asm volatile("cp.async.cg.shared.global [%0], [%1], 16;" :: "r"(dst), "l"(src))
#define CPA_COMMIT() asm volatile("cp.async.commit_group;" ::: "memory")
#define CPA_WAIT0()  asm volatile("cp.async.wait_group 0;" ::: "memory")
#define CPA_WAIT1()  asm volatile("cp.async.wait_group 1;" ::: "memory")

__device__ __forceinline__ void ldsm4(uint32_t* r, uint32_t addr) {
    asm volatile("ldmatrix.sync.aligned.m8n8.x4.shared.b16 {%0,%1,%2,%3}, [%4];"
        : "=r"(r[0]), "=r"(r[1]), "=r"(r[2]), "=r"(r[3]) : "r"(addr));
}
__device__ __forceinline__ void mma16816(float* c, const uint32_t* a, const uint32_t* b) {
    asm volatile("mma.sync.aligned.m16n8k16.row.col.f32.f16.f16.f32 "
        "{%0,%1,%2,%3}, {%4,%5,%6,%7}, {%8,%9}, {%0,%1,%2,%3};"
        : "+f"(c[0]), "+f"(c[1]), "+f"(c[2]), "+f"(c[3])
        : "r"(a[0]), "r"(a[1]), "r"(a[2]), "r"(a[3]), "r"(b[0]), "r"(b[1]));
}
#define SWZ(o) ((o) ^ (((o) >> 3) & 0x70))

// ---------------- scratch globals ----------------
__device__ int   g_cnt[NEXP];
__device__ int   g_tok[NEXP * CAP];
__device__ float g_w[NEXP * CAP];
__device__ __half g_x16[N_TOK * DIM];
__device__ __half g_wgu16[(size_t)NEXP * 2 * IDIM * DIM];
__device__ __half g_wd16[(size_t)NEXP * DIM * IDIM];
__device__ __half g_act16[(size_t)NEXP * CAP * IDIM];

// ---------------- small kernels ----------------
__global__ void k_init_y(float* __restrict__ y) {
    int idx = blockIdx.x * blockDim.x + threadIdx.x;
    if (idx < N_TOK * DIM) y[idx] = 0.f;
}

// fp32 -> fp16 (x) + counter zeroing fused in
__global__ void k_cvt_x(const float4* __restrict__ s, uint2* __restrict__ o, int n4) {
    if (blockIdx.x == 0 && threadIdx.x < NEXP) g_cnt[threadIdx.x] = 0;
    for (int i = blockIdx.x * blockDim.x + threadIdx.x; i < n4; i += gridDim.x * blockDim.x) {
        float4 v = s[i];
        __half2 p0 = __floats2half2_rn(v.x, v.y);
        __half2 p1 = __floats2half2_rn(v.z, v.w);
        o[i] = make_uint2(*(uint32_t*)&p0, *(uint32_t*)&p1);
    }
}

__global__ void k_cvt_h(const float4* __restrict__ s, uint2* __restrict__ o, int n4) {
    for (int i = blockIdx.x * blockDim.x + threadIdx.x; i < n4; i += gridDim.x * blockDim.x) {
        float4 v = s[i];
        __half2 p0 = __floats2half2_rn(v.x, v.y);
        __half2 p1 = __floats2half2_rn(v.z, v.w);
        o[i] = make_uint2(*(uint32_t*)&p0, *(uint32_t*)&p1);
    }
}

// router: one warp per token, float4-vectorized loads
__global__ void k_router(const float* __restrict__ x, const float* __restrict__ rw,
                         const float* __restrict__ rb) {
    int gw = (blockIdx.x * blockDim.x + threadIdx.x) >> 5;
    int lane = threadIdx.x & 31;
    if (gw >= N_TOK) return;
    const float4* xr = (const float4*)(x + (size_t)gw * DIM);
    float acc[NEXP];
#pragma unroll
    for (int e = 0; e < NEXP; e++) acc[e] = 0.f;
#pragma unroll
    for (int it = 0; it < DIM / (32 * 4); it++) {
        int q = it * 32 + lane;                 // float4 index within row
        float4 xv = xr[q];
#pragma unroll
        for (int e = 0; e < NEXP; e++) {
            float4 wv = ((const float4*)(rw + e * DIM))[q];
            acc[e] = fmaf(xv.x, wv.x, acc[e]);
            acc[e] = fmaf(xv.y, wv.y, acc[e]);
            acc[e] = fmaf(xv.z, wv.z, acc[e]);
            acc[e] = fmaf(xv.w, wv.w, acc[e]);
        }
    }
#pragma unroll
    for (int e = 0; e < NEXP; e++)
#pragma unroll
        for (int off = 16; off; off >>= 1) acc[e] += __shfl_down_sync(0xffffffffu, acc[e], off);
    if (lane == 0) {
        float lg[NEXP];
#pragma unroll
        for (int e = 0; e < NEXP; e++) lg[e] = acc[e] + rb[e];
        int sel[4]; float sv[4]; unsigned used = 0;
#pragma unroll
        for (int k = 0; k < 4; k++) {
            int bi = 0; float bv = -3.4e38f;
#pragma unroll
            for (int e = 0; e < NEXP; e++)
                if (!((used >> e) & 1u) && lg[e] > bv) { bv = lg[e]; bi = e; }
            used |= (1u << bi); sel[k] = bi; sv[k] = bv;
        }
        float s = 0.f, ex[4];
#pragma unroll
        for (int k = 0; k < 4; k++) { ex[k] = __expf(sv[k] - sv[0]); s += ex[k]; }
        float inv = 1.f / s;
#pragma unroll
        for (int k = 0; k < 4; k++) {
            int e = sel[k];
            int pos = atomicAdd(&g_cnt[e], 1);
            g_tok[e * CAP + pos] = gw;
            g_w[e * CAP + pos] = ex[k] * inv;
        }
    }
}

// ---------------- gate_up grouped GEMM (single fp16, 3-stage) --------------
// Experts [e0, e0+gridDim.z). CTA: 128 tokens x (64g + 64u). 16 k-chunks.
__global__ __launch_bounds__(256, 2) void k_gateup(const float* __restrict__ bgu, int e0) {
    int e = e0 + blockIdx.z;
    int cnt = g_cnt[e];
    int m0 = blockIdx.y * 128;
    if (m0 >= cnt) return;
    int n0 = blockIdx.x * 64;

    extern __shared__ char dsm[];
    __shared__ int s_tok[128];
    int t = threadIdx.x;
    uint32_t dyn = smem_u32(dsm);
    uint32_t tb = (dyn + 1023) & ~1023u;

    if (t < 128) {
        int r = m0 + t; if (r >= cnt) r = cnt - 1;
        s_tok[t] = g_tok[e * CAP + r];
    }
    __syncthreads();

    const __half* wgu = g_wgu16 + (size_t)e * 2 * IDIM * DIM;

    auto issue = [&](int c) {
        int col0 = c * 64;
        uint32_t base = tb + (c % 3) * 32768;
#pragma unroll
        for (int it = 0; it < 4; it++) {
            int idx = it * 256 + t; int r = idx >> 3; int gq = idx & 7;
            uint32_t off = SWZ(r * 128 + gq * 16);
            CPA16(base + off, g_x16 + (size_t)s_tok[r] * DIM + col0 + gq * 8);
        }
#pragma unroll
        for (int it = 0; it < 4; it++) {
            int idx = it * 256 + t; int r = idx >> 3; int gq = idx & 7;
            uint32_t off = SWZ(r * 128 + gq * 16);
            int wrow = (r < 64) ? (n0 + r) : (IDIM + n0 + r - 64);
            CPA16(base + 16384 + off, wgu + (size_t)wrow * DIM + col0 + gq * 8);
        }
        CPA_COMMIT();
    };

    int warp = t >> 5, lane = t & 31;
    int wm = warp & 3, wn = warp >> 2;
    float accg[2][4][4] = {}, accu[2][4][4] = {};

    // pre-swizzled lane bases; k-step applied with XOR (bits 5-6 of unswizzled
    // base are 0, swizzle mask depends only on row bits -> SWZ(x+ko)==SWZ(x)^ko)
    uint32_t arow[2], grow[2], urow[2];
#pragma unroll
    for (int mt = 0; mt < 2; mt++)
        arow[mt] = SWZ((wm * 32 + mt * 16 + (lane & 15)) * 128 + ((lane >> 4) << 4));
#pragma unroll
    for (int nt = 0; nt < 2; nt++) {
        int rg = wn * 32 + nt * 16 + ((lane >> 4) << 3) + (lane & 7);
        uint32_t kb = ((lane >> 3) & 1) << 4;
        grow[nt] = SWZ(rg * 128 + kb);
        urow[nt] = SWZ((rg + 64) * 128 + kb);
    }

    const int NC = 16;
    issue(0); issue(1);
    for (int c = 0; c < NC; c++) {
        if (c + 1 < NC) CPA_WAIT1(); else CPA_WAIT0();
        __syncthreads();
        if (c + 2 < NC) issue(c + 2);
        uint32_t base = tb + (c % 3) * 32768;
#pragma unroll
        for (int kk = 0; kk < 4; kk++) {
            uint32_t ko = kk * 32;
            uint32_t ah[2][4], bg[2][4], bu[2][4];
#pragma unroll
            for (int mt = 0; mt < 2; mt++) ldsm4(ah[mt], base + (arow[mt] ^ ko));
#pragma unroll
            for (int nt = 0; nt < 2; nt++) {
                ldsm4(bg[nt], base + 16384 + (grow[nt] ^ ko));
                ldsm4(bu[nt], base + 16384 + (urow[nt] ^ ko));
            }
#pragma unroll
            for (int mt = 0; mt < 2; mt++)
#pragma unroll
                for (int nt = 0; nt < 4; nt++) {
                    mma16816(accg[mt][nt], ah[mt], &bg[nt >> 1][(nt & 1) * 2]);
                    mma16816(accu[mt][nt], ah[mt], &bu[nt >> 1][(nt & 1) * 2]);
                }
        }
    }

    // epilogue: bias + clamped SwiGLU -> fp16 activations
#pragma unroll
    for (int mt = 0; mt < 2; mt++) {
        int r0 = m0 + wm * 32 + mt * 16 + (lane >> 2);
        int r1 = r0 + 8;
#pragma unroll
        for (int nt = 0; nt < 4; nt++) {
            int jg = n0 + wn * 32 + nt * 8 + (lane & 3) * 2;
            float bg0 = bgu[e * 2 * IDIM + jg],        bg1 = bgu[e * 2 * IDIM + jg + 1];
            float bu0 = bgu[e * 2 * IDIM + IDIM + jg], bu1 = bgu[e * 2 * IDIM + IDIM + jg + 1];
#pragma unroll
            for (int hh = 0; hh < 2; hh++) {
                int r = hh ? r1 : r0;
                if (r >= cnt) continue;
                float g0 = accg[mt][nt][hh * 2 + 0] + bg0;
                float g1 = accg[mt][nt][hh * 2 + 1] + bg1;
                float u0 = accu[mt][nt][hh * 2 + 0] + bu0;
                float u1 = accu[mt][nt][hh * 2 + 1] + bu1;
                g0 = fminf(g0, 7.f); g1 = fminf(g1, 7.f);
                u0 = fminf(fmaxf(u0, -7.f), 7.f); u1 = fminf(fmaxf(u1, -7.f), 7.f);
                float a0 = (u0 + 1.f) * g0 / (1.f + __expf(-1.702f * g0));
                float a1 = (u1 + 1.f) * g1 / (1.f + __expf(-1.702f * g1));
                __half2 hv = __floats2half2_rn(a0, a1);
                *(uint32_t*)(g_act16 + ((size_t)e * CAP + r) * IDIM + jg) = *(uint32_t*)&hv;
            }
        }
    }
}

// ---------------- down grouped GEMM (single fp16, 3-stage) + combine ------
// Experts [e0, e0+gridDim.z). CTA: 128 tokens x 128 out dims. 32 k-chunks.
__global__ __launch_bounds__(256, 2) void k_down(const float* __restrict__ bd,
                                                 float* __restrict__ y, int e0) {
    int e = e0 + blockIdx.z;
    int cnt = g_cnt[e];
    int m0 = blockIdx.y * 128;
    if (m0 >= cnt) return;
    int nn0 = blockIdx.x * 128;

    extern __shared__ char dsm[];
    int t = threadIdx.x;
    uint32_t dyn = smem_u32(dsm);
    uint32_t tb = (dyn + 1023) & ~1023u;

    const __half* a_g = g_act16 + ((size_t)e * CAP + m0) * IDIM;
    const __half* wd  = g_wd16 + (size_t)e * DIM * IDIM;

    auto issue = [&](int c) {
        int col0 = c * 64;
        uint32_t base = tb + (c % 3) * 32768;
#pragma unroll
        for (int it = 0; it < 4; it++) {
            int idx = it * 256 + t; int r = idx >> 3; int gq = idx & 7;
            uint32_t off = SWZ(r * 128 + gq * 16);
            CPA16(base + off, a_g + (size_t)r * IDIM + col0 + gq * 8);
        }
#pragma unroll
        for (int it = 0; it < 4; it++) {
            int idx = it * 256 + t; int r = idx >> 3; int gq = idx & 7;
            uint32_t off = SWZ(r * 128 + gq * 16);
            CPA16(base + 16384 + off, wd + (size_t)(nn0 + r) * IDIM + col0 + gq * 8);
        }
        CPA_COMMIT();
    };

    int warp = t >> 5, lane = t & 31;
    int wm = warp & 3, wn = warp >> 2;
    float acc[2][8][4] = {};

    uint32_t arow[2], brow[4];
#pragma unroll
    for (int mt = 0; mt < 2; mt++)
        arow[mt] = SWZ((wm * 32 + mt * 16 + (lane & 15)) * 128 + ((lane >> 4) << 4));
#pragma unroll
    for (int nt = 0; nt < 4; nt++) {
        int rb_ = wn * 64 + nt * 16 + ((lane >> 4) << 3) + (lane & 7);
        brow[nt] = SWZ(rb_ * 128 + (((lane >> 3) & 1) << 4));
    }

    const int NC = 32;
    issue(0); issue(1);
    for (int c = 0; c < NC; c++) {
        if (c + 1 < NC) CPA_WAIT1(); else CPA_WAIT0();
        __syncthreads();
        if (c + 2 < NC) issue(c + 2);
        uint32_t base = tb + (c % 3) * 32768;
#pragma unroll
        for (int kk = 0; kk < 4; kk++) {
            uint32_t ko = kk * 32;
            uint32_t ah[2][4], b[4][4];
#pragma unroll
            for (int mt = 0; mt < 2; mt++) ldsm4(ah[mt], base + (arow[mt] ^ ko));
#pragma unroll
            for (int nt = 0; nt < 4; nt++) ldsm4(b[nt], base + 16384 + (brow[nt] ^ ko));
#pragma unroll
            for (int mt = 0; mt < 2; mt++)
#pragma unroll
                for (int nt = 0; nt < 8; nt++)
                    mma16816(acc[mt][nt], ah[mt], &b[nt >> 1][(nt & 1) * 2]);
        }
    }

    // epilogue: + bias, * combine weight, atomicAdd into y
#pragma unroll
    for (int mt = 0; mt < 2; mt++) {
        int r0 = m0 + wm * 32 + mt * 16 + (lane >> 2);
        int r1 = r0 + 8;
        int   tok0 = 0, tok1 = 0; float w0 = 0.f, w1 = 0.f;
        bool v0 = r0 < cnt, v1 = r1 < cnt;
        if (v0) { tok0 = g_tok[e * CAP + r0]; w0 = g_w[e * CAP + r0]; }
        if (v1) { tok1 = g_tok[e * CAP + r1]; w1 = g_w[e * CAP + r1]; }
#pragma unroll
        for (int nt = 0; nt < 8; nt++) {
            int n = nn0 + wn * 64 + nt * 8 + (lane & 3) * 2;
            float b0 = bd[e * DIM + n], b1 = bd[e * DIM + n + 1];
            if (v0) {
                atomicAdd(&y[(size_t)tok0 * DIM + n],     w0 * (acc[mt][nt][0] + b0));
                atomicAdd(&y[(size_t)tok0 * DIM + n + 1], w0 * (acc[mt][nt][1] + b1));
            }
            if (v1) {
                atomicAdd(&y[(size_t)tok1 * DIM + n],     w1 * (acc[mt][nt][2] + b0));
                atomicAdd(&y[(size_t)tok1 * DIM + n + 1], w1 * (acc[mt][nt][3] + b1));
            }
        }
    }
}

// ---------------------------------------------------------------------------
extern "C" void kernel_launch(void* const* d_in, const int* in_sizes, int n_in,
                              void* d_out, int out_size) {
    const float* x   = (const float*)d_in[0];
    const float* rw  = (const float*)d_in[1];
    const float* rb  = (const float*)d_in[2];
    const float* wgu = (const float*)d_in[3];
    const float* bgu = (const float*)d_in[4];
    const float* wd  = (const float*)d_in[5];
    const float* bd  = (const float*)d_in[6];
    float* y = (float*)d_out;

    // one-time setup — same 2-side-stream resource set as the passing rounds
    static cudaStream_t s2 = nullptr, s3 = nullptr;
    static cudaEvent_t ev_root = nullptr, ev_main = nullptr, ev_wguA = nullptr,
                       ev_wd = nullptr, ev_d2 = nullptr, ev_d3 = nullptr;
    if (!s2) {
        cudaStreamCreateWithFlags(&s2, cudaStreamNonBlocking);
        cudaStreamCreateWithFlags(&s3, cudaStreamNonBlocking);
        cudaEventCreateWithFlags(&ev_root, cudaEventDisableTiming);
        cudaEventCreateWithFlags(&ev_main, cudaEventDisableTiming);
        cudaEventCreateWithFlags(&ev_wguA, cudaEventDisableTiming);
        cudaEventCreateWithFlags(&ev_wd, cudaEventDisableTiming);
        cudaEventCreateWithFlags(&ev_d2, cudaEventDisableTiming);
        cudaEventCreateWithFlags(&ev_d3, cudaEventDisableTiming);
        cudaFuncSetAttribute(k_gateup, cudaFuncAttributeMaxDynamicSharedMemorySize, SMEM_SZ);
        cudaFuncSetAttribute(k_down,   cudaFuncAttributeMaxDynamicSharedMemorySize, SMEM_SZ);
    }

    __half *x16, *gu16, *wd16;
    cudaGetSymbolAddress((void**)&x16,  g_x16);
    cudaGetSymbolAddress((void**)&gu16, g_wgu16);
    cudaGetSymbolAddress((void**)&wd16, g_wd16);

    const size_t WGU_E = (size_t)2 * IDIM * DIM;   // wgu elems per expert

    // fork side streams off the main (capture) stream
    cudaEventRecord(ev_root, 0);
    cudaStreamWaitEvent(s2, ev_root, 0);
    cudaStreamWaitEvent(s3, ev_root, 0);

    // s3: chain-A wgu slice first (unblocks main ASAP), then chain-C slice,
    //     then y-zero + wd conversion (all done long before any down runs)
    k_cvt_h<<<3072, 256, 0, s3>>>((const float4*)(wgu),
                                  (uint2*)(gu16), (int)(3 * WGU_E / 4));
    cudaEventRecord(ev_wguA, s3);
    k_cvt_h<<<2048, 256, 0, s3>>>((const float4*)(wgu + 6 * WGU_E),
                                  (uint2*)(gu16 + 6 * WGU_E), (int)(2 * WGU_E / 4));
    k_init_y<<<(N_TOK * DIM + 255) / 256, 256, 0, s3>>>(y);
    k_cvt_h<<<4096, 256, 0, s3>>>((const float4*)wd, (uint2*)wd16, NEXP * DIM * IDIM / 4);
    cudaEventRecord(ev_wd, s3);

    // s2: chain-B wgu slice (in-stream for its own gateups)
    k_cvt_h<<<3072, 256, 0, s2>>>((const float4*)(wgu + 3 * WGU_E),
                                  (uint2*)(gu16 + 3 * WGU_E), (int)(3 * WGU_E / 4));

    // main: x conversion (+ counter zero fused) -> vectorized router
    k_cvt_x<<<1024, 256>>>((const float4*)x, (uint2*)x16, N_TOK * DIM / 4);
    k_router<<<(N_TOK * 32) / 256, 256>>>(x, rw, rb);
    cudaEventRecord(ev_main, 0);

    // ---- 3 expert chains, each: ALL gateups first, then ALL downs ----
    // chain A (main, experts 0-2)
    cudaStreamWaitEvent(0, ev_wguA, 0);
    k_gateup<<<dim3(IDIM / 64, CAP / 128, 3), 256, SMEM_SZ>>>(bgu, 0);
    cudaStreamWaitEvent(0, ev_wd, 0);
    k_down<<<dim3(DIM / 128, CAP / 128, 3), 256, SMEM_SZ>>>(bd, y, 0);

    // chain B (s2, experts 3-5)
    cudaStreamWaitEvent(s2, ev_main, 0);
    k_gateup<<<dim3(IDIM / 64, CAP / 128, 3), 256, SMEM_SZ, s2>>>(bgu, 3);
    cudaStreamWaitEvent(s2, ev_wd, 0);
    k_down<<<dim3(DIM / 128, CAP / 128, 3), 256, SMEM_SZ, s2>>>(bd, y, 3);
    cudaEventRecord(ev_d2, s2);

    // chain C (s3, experts 6-7): wgu slice, wd and y are all in-stream
    cudaStreamWaitEvent(s3, ev_main, 0);
    k_gateup<<<dim3(IDIM / 64, CAP / 128, 2), 256, SMEM_SZ, s3>>>(bgu, 6);
    k_down<<<dim3(DIM / 128, CAP / 128, 2), 256, SMEM_SZ, s3>>>(bd, y, 6);
    cudaEventRecord(ev_d3, s3);

    // join side chains back into the main stream
    cudaStreamWaitEvent(0, ev_d2, 0);
    cudaStreamWaitEvent(0, ev_d3, 0);
}